// round 9
// baseline (speedup 1.0000x reference)
#include <cuda_runtime.h>
#include <cuda_bf16.h>
#include <cuda_fp16.h>
#include <cstdint>

// Problem constants
#define Bdim 2
#define Tdim 2048
#define Cdim 1024
#define Hn   16
#define HDd  64
#define Mrows (Bdim * Tdim)   // 4096
#define N3    (3 * Cdim)      // 3072

// ---------------------------------------------------------------------------
// Scratch (__device__ globals; allocation-free rule)
// ---------------------------------------------------------------------------
__device__ __half g_x_hi[Mrows * Cdim];
__device__ __half g_x_lo[Mrows * Cdim];
__device__ __half g_wa[N3 * Cdim];        // [N=3072][K=1024], fp16 single
__device__ __half g_wp[Cdim * Cdim];      // [N=1024][K=1024], fp16 single
__device__ __half g_y_hi[Mrows * Cdim];   // attn output, [B*T][C], fp16 split
__device__ __half g_y_lo[Mrows * Cdim];

// q split fp16 (pre-scaled by 1/8); k, v single fp16. Head-major [B*H][T][HD]
__device__ __half g_qh[Bdim * Hn * Tdim * HDd];
__device__ __half g_ql[Bdim * Hn * Tdim * HDd];
__device__ __half g_k [Bdim * Hn * Tdim * HDd];
__device__ __half g_v [Bdim * Hn * Tdim * HDd];

// ---------------------------------------------------------------------------
// PTX helpers (plain sm_103-safe)
// ---------------------------------------------------------------------------
__device__ __forceinline__ uint32_t smem_u32(const void* p) {
    uint32_t a;
    asm("{ .reg .u64 t; cvta.to.shared.u64 t, %1; cvt.u32.u64 %0, t; }"
        : "=r"(a) : "l"(p));
    return a;
}

#define LDSM4(r, addr) \
    asm volatile("ldmatrix.sync.aligned.m8n8.x4.shared.b16 {%0,%1,%2,%3}, [%4];" \
        : "=r"((r)[0]), "=r"((r)[1]), "=r"((r)[2]), "=r"((r)[3]) : "r"(addr))

#define LDSM4T(r, addr) \
    asm volatile("ldmatrix.sync.aligned.m8n8.x4.trans.shared.b16 {%0,%1,%2,%3}, [%4];" \
        : "=r"((r)[0]), "=r"((r)[1]), "=r"((r)[2]), "=r"((r)[3]) : "r"(addr))

#define MMA_F16(c, a, b0, b1) \
    asm volatile("mma.sync.aligned.m16n8k16.row.col.f32.f16.f16.f32 " \
        "{%0,%1,%2,%3}, {%4,%5,%6,%7}, {%8,%9}, {%0,%1,%2,%3};" \
        : "+f"((c)[0]), "+f"((c)[1]), "+f"((c)[2]), "+f"((c)[3]) \
        : "r"((a)[0]), "r"((a)[1]), "r"((a)[2]), "r"((a)[3]), "r"(b0), "r"(b1))

#define CP_ASYNC16(dst, src) \
    asm volatile("cp.async.cg.shared.global [%0], [%1], 16;" :: "r"(dst), "l"(src))
#define CP_COMMIT() asm volatile("cp.async.commit_group;")

// fp16 split pack
__device__ __forceinline__ void pack_split2h(float v0, float v1,
                                             uint32_t& hi, uint32_t& lo) {
    __half h0 = __float2half_rn(v0);
    __half l0 = __float2half_rn(v0 - __half2float(h0));
    __half h1 = __float2half_rn(v1);
    __half l1 = __float2half_rn(v1 - __half2float(h1));
    __half2 hh(h0, h1), ll(l0, l1);
    hi = *(uint32_t*)&hh;
    lo = *(uint32_t*)&ll;
}

__device__ __forceinline__ uint32_t pack2h(float v0, float v1) {
    __half2 h(__float2half_rn(v0), __float2half_rn(v1));
    return *(uint32_t*)&h;
}

// ---------------------------------------------------------------------------
// Prep kernels
// ---------------------------------------------------------------------------
__global__ __launch_bounds__(256) void prep_x_kernel(const float* __restrict__ x) {
    int i = (blockIdx.x * 256 + threadIdx.x) * 4;
    float4 v = *(const float4*)&x[i];
    uint32_t h0, l0, h1, l1;
    pack_split2h(v.x, v.y, h0, l0);
    pack_split2h(v.z, v.w, h1, l1);
    *(uint32_t*)&g_x_hi[i]     = h0;
    *(uint32_t*)&g_x_hi[i + 2] = h1;
    *(uint32_t*)&g_x_lo[i]     = l0;
    *(uint32_t*)&g_x_lo[i + 2] = l1;
}

// Transpose W [K, N] -> Wt [N, K] fp16 single
__global__ __launch_bounds__(256) void prep_w_kernel(
    const float* __restrict__ W, __half* __restrict__ Wt, int K, int N) {
    __shared__ float tile[32][33];
    int n0 = blockIdx.x * 32, k0 = blockIdx.y * 32;
    int tx = threadIdx.x & 31, ty = threadIdx.x >> 5;   // 32 x 8
    #pragma unroll
    for (int r = 0; r < 32; r += 8)
        tile[ty + r][tx] = W[(size_t)(k0 + ty + r) * N + n0 + tx];
    __syncthreads();
    #pragma unroll
    for (int r = 0; r < 32; r += 8) {
        float v = tile[tx][ty + r];
        Wt[(size_t)(n0 + ty + r) * K + k0 + tx] = __float2half_rn(v);
    }
}

// ---------------------------------------------------------------------------
// mma.sync fp16 A-split 2-term GEMM: D[128x128] = (Ah+Al)[Mx1024] * B^T + bias
// 4-warp CTA (128 thr), warps 2x2, warp tile 64x64 -> B frags reused x4.
// 2-stage cp.async pipeline, BK=32. Packed-swizzled smem (zero padding).
// mode 0: write q fp16-split (x0.125) / k,v fp16-single head-major.
// mode 1: write fp32 out row-major.
// ---------------------------------------------------------------------------
#define GARR8  8192                 // one array (128x32 fp16 packed)
#define GSTG   (3 * GARR8)          // 24576 per stage (Ah, Al, B)
#define GSMEM  (2 * GSTG)           // 49152

// packed smem byte offset for logical row m (0..127), 16B-chunk c (0..3)
__device__ __forceinline__ uint32_t pk_off(int m, int c) {
    return (uint32_t)((m >> 1) * 128 + (m & 1) * 64 + ((c ^ ((m >> 1) & 3)) << 4));
}

__global__ __launch_bounds__(128, 2)
void gemm_f16x2_kernel(const __half* __restrict__ Ah,
                       const __half* __restrict__ Al,
                       const __half* __restrict__ Bw,
                       const float* __restrict__ bias,
                       float* __restrict__ out, int mode) {
    extern __shared__ __align__(16) char dynsm[];

    const int tid  = threadIdx.x;
    const int lane = tid & 31;
    const int wid  = tid >> 5;       // 0..3
    const int wm   = wid & 1;        // warp row: 64 rows each
    const int wn   = wid >> 1;       // warp col: 64 cols each
    const int n0 = blockIdx.x * 128;
    const int m0 = blockIdx.y * 128;

    const uint32_t uS = smem_u32(dynsm);

    float acc[4][8][4] = {};

    auto issue = [&](int ch) {
        const uint32_t sb = uS + (uint32_t)(ch & 1) * GSTG;
        const int k0 = ch * 32;
        #pragma unroll
        for (int it = 0; it < 4; ++it) {
            int idx = tid + it * 128;        // 512 transfers per array
            int m = idx >> 2;
            int c = idx & 3;
            uint32_t so = pk_off(m, c);
            size_t ga = (size_t)(m0 + m) * Cdim + k0 + c * 8;
            size_t gb = (size_t)(n0 + m) * Cdim + k0 + c * 8;
            CP_ASYNC16(sb + so,             Ah + ga);
            CP_ASYNC16(sb + GARR8 + so,     Al + ga);
            CP_ASYNC16(sb + 2 * GARR8 + so, Bw + gb);
        }
        CP_COMMIT();
    };

    // per-lane ldmatrix address precomputes (row part + xor key)
    uint32_t arow[4], axor[4], brow[4], bxor[4];
    #pragma unroll
    for (int mt = 0; mt < 4; ++mt) {
        int m = wm * 64 + mt * 16 + (lane & 15);
        arow[mt] = (uint32_t)((m >> 1) * 128 + (m & 1) * 64);
        axor[mt] = (uint32_t)((m >> 1) & 3);
    }
    #pragma unroll
    for (int np = 0; np < 4; ++np) {
        int n = wn * 64 + np * 16 + (lane & 15);
        brow[np] = (uint32_t)((n >> 1) * 128 + (n & 1) * 64);
        bxor[np] = (uint32_t)((n >> 1) & 3);
    }
    const int chalf = lane >> 4;   // which 16B chunk within the k16

    const int NCH = Cdim / 32;   // 32
    issue(0);

    for (int ch = 0; ch < NCH; ++ch) {
        const bool more = (ch + 1 < NCH);
        if (more) issue(ch + 1);
        if (more) { asm volatile("cp.async.wait_group 1;"); }
        else      { asm volatile("cp.async.wait_group 0;"); }
        __syncthreads();

        const uint32_t sb  = uS + (uint32_t)(ch & 1) * GSTG;
        const uint32_t sAh = sb, sAl = sb + GARR8, sB = sb + 2 * GARR8;

        #pragma unroll
        for (int kk = 0; kk < 2; ++kk) {
            const int cix = kk * 2 + chalf;     // chunk index 0..3
            uint32_t ah[16], al[16], bh[16];
            #pragma unroll
            for (int mt = 0; mt < 4; ++mt) {
                uint32_t ao = arow[mt] + (uint32_t)((cix ^ axor[mt]) << 4);
                LDSM4(ah + mt * 4, sAh + ao);
                LDSM4(al + mt * 4, sAl + ao);
            }
            #pragma unroll
            for (int np = 0; np < 4; ++np) {
                uint32_t bo = brow[np] + (uint32_t)((cix ^ bxor[np]) << 4);
                LDSM4(bh + np * 4, sB + bo);
            }
            // pass 1: ah * b (32 MMAs, all distinct accumulators)
            #pragma unroll
            for (int np = 0; np < 4; ++np)
                #pragma unroll
                for (int mt = 0; mt < 4; ++mt)
                    #pragma unroll
                    for (int hf = 0; hf < 2; ++hf)
                        MMA_F16(acc[mt][np * 2 + hf], ah + mt * 4,
                                bh[np * 4 + hf], bh[np * 4 + 2 + hf]);
            // pass 2: al * b
            #pragma unroll
            for (int np = 0; np < 4; ++np)
                #pragma unroll
                for (int mt = 0; mt < 4; ++mt)
                    #pragma unroll
                    for (int hf = 0; hf < 2; ++hf)
                        MMA_F16(acc[mt][np * 2 + hf], al + mt * 4,
                                bh[np * 4 + hf], bh[np * 4 + 2 + hf]);
        }
        __syncthreads();
    }

    // Epilogue: warp covers rows [wm*64, wm*64+64), cols [wn*64, wn*64+64)
    if (mode == 0) {
        const int ncol0 = n0 + wn * 64;
        const int which = ncol0 >> 10;
        const int hh    = (ncol0 & 1023) >> 6;
        #pragma unroll
        for (int mt = 0; mt < 4; ++mt) {
            const int rg0 = m0 + wm * 64 + mt * 16 + (lane >> 2);
            const int bb  = rg0 >> 11;
            const int t0  = rg0 & 2047;
            const size_t rbase = (((size_t)bb * Hn + hh) * Tdim + t0) * HDd;
            #pragma unroll
            for (int nt = 0; nt < 8; ++nt) {
                const int d = nt * 8 + (lane & 3) * 2;
                const float2 bv = *(const float2*)&bias[ncol0 + d];
                float v00 = acc[mt][nt][0] + bv.x;
                float v01 = acc[mt][nt][1] + bv.y;
                float v10 = acc[mt][nt][2] + bv.x;
                float v11 = acc[mt][nt][3] + bv.y;
                if (which == 0) {
                    uint32_t hi, lo;
                    pack_split2h(v00 * 0.125f, v01 * 0.125f, hi, lo);
                    *(uint32_t*)&g_qh[rbase + d] = hi;
                    *(uint32_t*)&g_ql[rbase + d] = lo;
                    pack_split2h(v10 * 0.125f, v11 * 0.125f, hi, lo);
                    *(uint32_t*)&g_qh[rbase + 8 * HDd + d] = hi;
                    *(uint32_t*)&g_ql[rbase + 8 * HDd + d] = lo;
                } else {
                    __half* dst = (which == 1) ? g_k : g_v;
                    *(uint32_t*)&dst[rbase + d]           = pack2h(v00, v01);
                    *(uint32_t*)&dst[rbase + 8 * HDd + d] = pack2h(v10, v11);
                }
            }
        }
    } else {
        #pragma unroll
        for (int mt = 0; mt < 4; ++mt) {
            const int rg0 = m0 + wm * 64 + mt * 16 + (lane >> 2);
            #pragma unroll
            for (int nt = 0; nt < 8; ++nt) {
                const int ncol = n0 + wn * 64 + nt * 8 + (lane & 3) * 2;
                const float2 bv = *(const float2*)&bias[ncol];
                float2 v0, v1;
                v0.x = acc[mt][nt][0] + bv.x;
                v0.y = acc[mt][nt][1] + bv.y;
                v1.x = acc[mt][nt][2] + bv.x;
                v1.y = acc[mt][nt][3] + bv.y;
                size_t base = (size_t)rg0 * Cdim + ncol;
                *(float2*)&out[base]            = v0;
                *(float2*)&out[base + 8 * Cdim] = v1;
            }
        }
    }
}

// ---------------------------------------------------------------------------
// mma.sync causal flash attention, fp16 A-split 2-term for QK^T and PV.
// BQ=128 (8 warps x 16 rows), BKV=64, HD=64. Double-buffered K/V cp.async.
// ---------------------------------------------------------------------------
#define ARS 144                      // row stride bytes
#define AQH 0
#define AQL 18432
#define AKV0 36864
#define KVSTG 18432                  // per-stage (K 9216 + V 9216)
#define ASMEM (AKV0 + 2 * KVSTG)     // 73728

__global__ __launch_bounds__(256, 2) void attn_mma_kernel() {
    extern __shared__ __align__(16) char asmem[];
    const int tid = threadIdx.x;
    const int lane = tid & 31;
    const int w = tid >> 5;
    const int qt = gridDim.x - 1 - blockIdx.x;   // heavy tiles first
    const int bh = blockIdx.y;

    const uint32_t uS = smem_u32(asmem);
    const size_t hbase = (size_t)bh * Tdim * HDd;
    const __half* qh = g_qh + hbase;
    const __half* ql = g_ql + hbase;
    const __half* kk = g_k + hbase;
    const __half* vv = g_v + hbase;

    auto issue_kv = [&](int kt) {
        const uint32_t sb = uS + AKV0 + (uint32_t)(kt & 1) * KVSTG;
        #pragma unroll
        for (int it = 0; it < 2; ++it) {
            int idx = tid + it * 256;
            int row = idx >> 3, c = idx & 7;
            uint32_t dst = row * ARS + c * 16;
            size_t src = (size_t)(kt * 64 + row) * HDd + c * 8;
            CP_ASYNC16(sb + dst,        kk + src);
            CP_ASYNC16(sb + 9216 + dst, vv + src);
        }
        CP_COMMIT();
    };

    // Q tile load (committed with KV stage 0)
    #pragma unroll
    for (int it = 0; it < 4; ++it) {
        int idx = tid + it * 256;
        int row = idx >> 3, c = idx & 7;
        uint32_t dst = row * ARS + c * 16;
        size_t src = (size_t)(qt * 128 + row) * HDd + c * 8;
        CP_ASYNC16(uS + AQH + dst, qh + src);
        CP_ASYNC16(uS + AQL + dst, ql + src);
    }
    issue_kv(0);

    const int r4 = lane >> 2;
    const int c2 = (lane & 3) * 2;
    float m0 = -1e30f, m1 = -1e30f, l0 = 0.f, l1 = 0.f;
    float O[8][4] = {};

    const int nkt = 2 * qt + 2;
    for (int kt = 0; kt < nkt; ++kt) {
        const bool more = (kt + 1 < nkt);
        if (more) issue_kv(kt + 1);
        if (more) { asm volatile("cp.async.wait_group 1;"); }
        else      { asm volatile("cp.async.wait_group 0;"); }
        __syncthreads();

        const uint32_t kvb = uS + AKV0 + (uint32_t)(kt & 1) * KVSTG;
        const uint32_t uK = kvb, uV = kvb + 9216;

        // ---- S = Q K^T (2-term fp16 split) ----
        float S[8][4] = {};
        #pragma unroll
        for (int k16 = 0; k16 < 4; ++k16) {
            const uint32_t qoff =
                (uint32_t)((w * 16 + (lane & 15)) * ARS + (lane >> 4) * 16 + k16 * 32);
            const uint32_t kfrag =
                (uint32_t)((lane & 15) * ARS + (lane >> 4) * 16 + k16 * 32);
            uint32_t aqh[4], aql[4], bk[16];
            LDSM4(aqh, uS + AQH + qoff);
            LDSM4(aql, uS + AQL + qoff);
            #pragma unroll
            for (int kp = 0; kp < 4; ++kp)
                LDSM4(bk + kp * 4, uK + kfrag + (uint32_t)(kp * 16) * ARS);
            // pass 1: qh*k (8 distinct accs)
            #pragma unroll
            for (int kp = 0; kp < 4; ++kp)
                #pragma unroll
                for (int hf = 0; hf < 2; ++hf)
                    MMA_F16(S[kp * 2 + hf], aqh, bk[kp * 4 + hf], bk[kp * 4 + 2 + hf]);
            // pass 2: ql*k
            #pragma unroll
            for (int kp = 0; kp < 4; ++kp)
                #pragma unroll
                for (int hf = 0; hf < 2; ++hf)
                    MMA_F16(S[kp * 2 + hf], aql, bk[kp * 4 + hf], bk[kp * 4 + 2 + hf]);
        }

        // ---- causal mask ----
        const int row0 = qt * 128 + w * 16 + r4;
        if (kt * 64 + 63 > qt * 128 + w * 16) {
            #pragma unroll
            for (int j = 0; j < 8; ++j) {
                const int cb = kt * 64 + j * 8 + c2;
                if (cb     > row0)     S[j][0] = -1e30f;
                if (cb + 1 > row0)     S[j][1] = -1e30f;
                if (cb     > row0 + 8) S[j][2] = -1e30f;
                if (cb + 1 > row0 + 8) S[j][3] = -1e30f;
            }
        }

        // ---- online softmax on fragments ----
        float mt0 = -1e30f, mt1 = -1e30f;
        #pragma unroll
        for (int j = 0; j < 8; ++j) {
            mt0 = fmaxf(mt0, fmaxf(S[j][0], S[j][1]));
            mt1 = fmaxf(mt1, fmaxf(S[j][2], S[j][3]));
        }
        mt0 = fmaxf(mt0, __shfl_xor_sync(0xffffffffu, mt0, 1));
        mt0 = fmaxf(mt0, __shfl_xor_sync(0xffffffffu, mt0, 2));
        mt1 = fmaxf(mt1, __shfl_xor_sync(0xffffffffu, mt1, 1));
        mt1 = fmaxf(mt1, __shfl_xor_sync(0xffffffffu, mt1, 2));
        const float mn0 = fmaxf(m0, mt0);
        const float mn1 = fmaxf(m1, mt1);
        const float sf0 = __expf(m0 - mn0);
        const float sf1 = __expf(m1 - mn1);
        m0 = mn0; m1 = mn1;

        float rs0 = 0.f, rs1 = 0.f;
        #pragma unroll
        for (int j = 0; j < 8; ++j) {
            S[j][0] = __expf(S[j][0] - m0);
            S[j][1] = __expf(S[j][1] - m0);
            S[j][2] = __expf(S[j][2] - m1);
            S[j][3] = __expf(S[j][3] - m1);
            rs0 += S[j][0] + S[j][1];
            rs1 += S[j][2] + S[j][3];
        }
        rs0 += __shfl_xor_sync(0xffffffffu, rs0, 1);
        rs0 += __shfl_xor_sync(0xffffffffu, rs0, 2);
        rs1 += __shfl_xor_sync(0xffffffffu, rs1, 1);
        rs1 += __shfl_xor_sync(0xffffffffu, rs1, 2);
        l0 = l0 * sf0 + rs0;
        l1 = l1 * sf1 + rs1;
        #pragma unroll
        for (int j = 0; j < 8; ++j) {
            O[j][0] *= sf0; O[j][1] *= sf0;
            O[j][2] *= sf1; O[j][3] *= sf1;
        }

        // ---- O += P V (2-term fp16 split P, single V) ----
        #pragma unroll
        for (int s = 0; s < 4; ++s) {
            uint32_t ph[4], pl[4];
            pack_split2h(S[2 * s][0],     S[2 * s][1],     ph[0], pl[0]);
            pack_split2h(S[2 * s][2],     S[2 * s][3],     ph[1], pl[1]);
            pack_split2h(S[2 * s + 1][0], S[2 * s + 1][1], ph[2], pl[2]);
            pack_split2h(S[2 * s + 1][2], S[2 * s + 1][3], ph[3], pl[3]);
            const uint32_t vrow =
                (uint32_t)((s * 16 + (lane & 7) + ((lane >> 3) & 1) * 8) * ARS
                           + (lane >> 4) * 16);
            uint32_t bv[16];
            #pragma unroll
            for (int np = 0; np < 4; ++np)
                LDSM4T(bv + np * 4, uV + vrow + np * 32);
            #pragma unroll
            for (int np = 0; np < 4; ++np) {
                MMA_F16(O[np * 2],     ph, bv[np * 4],     bv[np * 4 + 1]);
                MMA_F16(O[np * 2 + 1], ph, bv[np * 4 + 2], bv[np * 4 + 3]);
            }
            #pragma unroll
            for (int np = 0; np < 4; ++np) {
                MMA_F16(O[np * 2],     pl, bv[np * 4],     bv[np * 4 + 1]);
                MMA_F16(O[np * 2 + 1], pl, bv[np * 4 + 2], bv[np * 4 + 3]);
            }
        }
        __syncthreads();
    }

    // ---- normalize + write split y (fp16 hi/lo for proj) ----
    const float inv0 = 1.f / l0, inv1 = 1.f / l1;
    const int b = bh >> 4, h = bh & 15;
    const int rg0 = b * Tdim + qt * 128 + w * 16 + r4;
    const size_t base0 = (size_t)rg0 * Cdim + h * HDd;
    #pragma unroll
    for (int j = 0; j < 8; ++j) {
        const int d = j * 8 + c2;
        uint32_t hi, lo;
        pack_split2h(O[j][0] * inv0, O[j][1] * inv0, hi, lo);
        *(uint32_t*)&g_y_hi[base0 + d] = hi;
        *(uint32_t*)&g_y_lo[base0 + d] = lo;
        pack_split2h(O[j][2] * inv1, O[j][3] * inv1, hi, lo);
        *(uint32_t*)&g_y_hi[base0 + 8 * Cdim + d] = hi;
        *(uint32_t*)&g_y_lo[base0 + 8 * Cdim + d] = lo;
    }
}

// ---------------------------------------------------------------------------
extern "C" void kernel_launch(void* const* d_in, const int* in_sizes, int n_in,
                              void* d_out, int out_size) {
    const float* x      = (const float*)d_in[0];
    const float* w_attn = (const float*)d_in[1];
    const float* b_attn = (const float*)d_in[2];
    const float* w_proj = (const float*)d_in[3];
    const float* b_proj = (const float*)d_in[4];
    float* out = (float*)d_out;

    static bool attr_set = false;
    if (!attr_set) {
        cudaFuncSetAttribute(gemm_f16x2_kernel,
                             cudaFuncAttributeMaxDynamicSharedMemorySize, GSMEM);
        cudaFuncSetAttribute(attn_mma_kernel,
                             cudaFuncAttributeMaxDynamicSharedMemorySize, ASMEM);
        attr_set = true;
    }

    __half *x_hi, *x_lo, *wa, *wp, *y_hi, *y_lo;
    cudaGetSymbolAddress((void**)&x_hi, g_x_hi);
    cudaGetSymbolAddress((void**)&x_lo, g_x_lo);
    cudaGetSymbolAddress((void**)&wa, g_wa);
    cudaGetSymbolAddress((void**)&wp, g_wp);
    cudaGetSymbolAddress((void**)&y_hi, g_y_hi);
    cudaGetSymbolAddress((void**)&y_lo, g_y_lo);

    // Prep: split x (fp16 hi/lo), transpose weights (fp16 single)
    prep_x_kernel<<<Mrows * Cdim / (256 * 4), 256>>>(x);
    {
        dim3 ga(N3 / 32, Cdim / 32);
        prep_w_kernel<<<ga, 256>>>(w_attn, wa, Cdim, N3);
        dim3 gp(Cdim / 32, Cdim / 32);
        prep_w_kernel<<<gp, 256>>>(w_proj, wp, Cdim, Cdim);
    }

    // QKV GEMM -> q fp16-split / k,v fp16-single head-major
    dim3 g1(N3 / 128, Mrows / 128);     // 24 x 32, 128-thread CTAs
    gemm_f16x2_kernel<<<g1, 128, GSMEM>>>(x_hi, x_lo, wa, b_attn, nullptr, 0);

    // Attention (tensor-core, fp16 2-term, double-buffered K/V)
    dim3 g2(Tdim / 128, Bdim * Hn);     // 16 x 32
    attn_mma_kernel<<<g2, 256, ASMEM>>>();

    // Proj GEMM
    dim3 g3(Cdim / 128, Mrows / 128);   // 8 x 32
    gemm_f16x2_kernel<<<g3, 128, GSMEM>>>(y_hi, y_lo, wp, b_proj, out, 1);
}

// round 10
// speedup vs baseline: 1.6224x; 1.6224x over previous
#include <cuda_runtime.h>
#include <cuda_fp16.h>
#include <cstdint>

// Problem constants
#define Bdim 2
#define Tdim 2048
#define Cdim 1024
#define Hn   16
#define HDd  64
#define Mrows (Bdim * Tdim)   // 4096
#define N3    (3 * Cdim)      // 3072

// ---------------------------------------------------------------------------
// Scratch (__device__ globals; allocation-free rule) — all single fp16
// ---------------------------------------------------------------------------
__device__ __half g_x [Mrows * Cdim];
__device__ __half g_wa[N3 * Cdim];        // [N=3072][K=1024]
__device__ __half g_wp[Cdim * Cdim];      // [N=1024][K=1024]
__device__ __half g_y [Mrows * Cdim];     // attn output, [B*T][C]

// q (pre-scaled by 1/8), k, v. Head-major [B*H][T][HD]
__device__ __half g_q[Bdim * Hn * Tdim * HDd];
__device__ __half g_k[Bdim * Hn * Tdim * HDd];
__device__ __half g_v[Bdim * Hn * Tdim * HDd];

// ---------------------------------------------------------------------------
// PTX helpers (plain sm_103-safe)
// ---------------------------------------------------------------------------
__device__ __forceinline__ uint32_t smem_u32(const void* p) {
    uint32_t a;
    asm("{ .reg .u64 t; cvta.to.shared.u64 t, %1; cvt.u32.u64 %0, t; }"
        : "=r"(a) : "l"(p));
    return a;
}

#define LDSM4(r, addr) \
    asm volatile("ldmatrix.sync.aligned.m8n8.x4.shared.b16 {%0,%1,%2,%3}, [%4];" \
        : "=r"((r)[0]), "=r"((r)[1]), "=r"((r)[2]), "=r"((r)[3]) : "r"(addr))

#define LDSM4T(r, addr) \
    asm volatile("ldmatrix.sync.aligned.m8n8.x4.trans.shared.b16 {%0,%1,%2,%3}, [%4];" \
        : "=r"((r)[0]), "=r"((r)[1]), "=r"((r)[2]), "=r"((r)[3]) : "r"(addr))

#define MMA_F16(c, a, b0, b1) \
    asm volatile("mma.sync.aligned.m16n8k16.row.col.f32.f16.f16.f32 " \
        "{%0,%1,%2,%3}, {%4,%5,%6,%7}, {%8,%9}, {%0,%1,%2,%3};" \
        : "+f"((c)[0]), "+f"((c)[1]), "+f"((c)[2]), "+f"((c)[3]) \
        : "r"((a)[0]), "r"((a)[1]), "r"((a)[2]), "r"((a)[3]), "r"(b0), "r"(b1))

#define CP_ASYNC16(dst, src) \
    asm volatile("cp.async.cg.shared.global [%0], [%1], 16;" :: "r"(dst), "l"(src))
#define CP_COMMIT() asm volatile("cp.async.commit_group;")

__device__ __forceinline__ uint32_t pack2h(float v0, float v1) {
    __half2 h(__float2half_rn(v0), __float2half_rn(v1));
    return *(uint32_t*)&h;
}

// ---------------------------------------------------------------------------
// Prep kernels
// ---------------------------------------------------------------------------
__global__ __launch_bounds__(256) void prep_x_kernel(const float* __restrict__ x) {
    int i = (blockIdx.x * 256 + threadIdx.x) * 4;
    float4 v = *(const float4*)&x[i];
    *(uint32_t*)&g_x[i]     = pack2h(v.x, v.y);
    *(uint32_t*)&g_x[i + 2] = pack2h(v.z, v.w);
}

// Transpose W [K, N] -> Wt [N, K] fp16 single
__global__ __launch_bounds__(256) void prep_w_kernel(
    const float* __restrict__ W, __half* __restrict__ Wt, int K, int N) {
    __shared__ float tile[32][33];
    int n0 = blockIdx.x * 32, k0 = blockIdx.y * 32;
    int tx = threadIdx.x & 31, ty = threadIdx.x >> 5;   // 32 x 8
    #pragma unroll
    for (int r = 0; r < 32; r += 8)
        tile[ty + r][tx] = W[(size_t)(k0 + ty + r) * N + n0 + tx];
    __syncthreads();
    #pragma unroll
    for (int r = 0; r < 32; r += 8) {
        float v = tile[tx][ty + r];
        Wt[(size_t)(n0 + ty + r) * K + k0 + tx] = __float2half_rn(v);
    }
}

// ---------------------------------------------------------------------------
// mma.sync fp16 GEMM: D[128x128] = A[Mx1024] * B[Nx1024]^T + bias
// 8 warps (4x2), warp tile 32x64, BK=32, 3-stage cp.async pipeline.
// Packed-swizzled smem (zero padding). Stage = 2 arrays x 8KB = 16KB.
// mode 0: write q (x0.125) / k / v fp16 head-major.
// mode 1: write fp32 out row-major.
// ---------------------------------------------------------------------------
#define GARR8  8192                 // one array (128x32 fp16 packed)
#define GSTG   (2 * GARR8)          // 16384 per stage (A, B)
#define GSMEM  (3 * GSTG)           // 49152

// packed smem byte offset for logical row m (0..127), 16B-chunk c (0..3)
__device__ __forceinline__ uint32_t pk_off(int m, int c) {
    return (uint32_t)((m >> 1) * 128 + (m & 1) * 64 + ((c ^ ((m >> 1) & 3)) << 4));
}

__global__ __launch_bounds__(256, 2)
void gemm_f16_kernel(const __half* __restrict__ A,
                     const __half* __restrict__ Bw,
                     const float* __restrict__ bias,
                     float* __restrict__ out, int mode) {
    extern __shared__ __align__(16) char dynsm[];

    const int tid  = threadIdx.x;
    const int lane = tid & 31;
    const int wid  = tid >> 5;
    const int wm   = wid & 3;        // warp row: 32 rows each
    const int wn   = wid >> 2;       // warp col: 64 cols each
    const int n0 = blockIdx.x * 128;
    const int m0 = blockIdx.y * 128;

    const uint32_t uS = smem_u32(dynsm);

    float acc[2][8][4] = {};

    auto issue = [&](int ch) {
        const uint32_t sb = uS + (uint32_t)(ch % 3) * GSTG;
        const int k0 = ch * 32;
        #pragma unroll
        for (int it = 0; it < 2; ++it) {
            int idx = tid + it * 256;
            int m = idx >> 2;
            int c = idx & 3;
            uint32_t so = pk_off(m, c);
            size_t ga = (size_t)(m0 + m) * Cdim + k0 + c * 8;
            size_t gb = (size_t)(n0 + m) * Cdim + k0 + c * 8;
            CP_ASYNC16(sb + so,         A + ga);
            CP_ASYNC16(sb + GARR8 + so, Bw + gb);
        }
        CP_COMMIT();
    };

    // per-lane ldmatrix address precomputes (row part + xor key)
    uint32_t arow[2], axor[2], brow[4], bxor[4];
    #pragma unroll
    for (int mt = 0; mt < 2; ++mt) {
        int m = wm * 32 + mt * 16 + (lane & 15);
        arow[mt] = (uint32_t)((m >> 1) * 128 + (m & 1) * 64);
        axor[mt] = (uint32_t)((m >> 1) & 3);
    }
    #pragma unroll
    for (int np = 0; np < 4; ++np) {
        int n = wn * 64 + np * 16 + (lane & 15);
        brow[np] = (uint32_t)((n >> 1) * 128 + (n & 1) * 64);
        bxor[np] = (uint32_t)((n >> 1) & 3);
    }
    const int chalf = lane >> 4;   // which 16B chunk within the k16

    const int NCH = Cdim / 32;   // 32
    issue(0);
    issue(1);

    for (int ch = 0; ch < NCH; ++ch) {
        if (ch + 1 < NCH) { asm volatile("cp.async.wait_group 1;"); }
        else              { asm volatile("cp.async.wait_group 0;"); }
        __syncthreads();
        if (ch + 2 < NCH) issue(ch + 2);

        const uint32_t sb = uS + (uint32_t)(ch % 3) * GSTG;
        const uint32_t sA = sb, sB = sb + GARR8;

        #pragma unroll
        for (int kk = 0; kk < 2; ++kk) {
            const int cix = kk * 2 + chalf;     // chunk index 0..3
            uint32_t ah[8], bh[16];
            #pragma unroll
            for (int mt = 0; mt < 2; ++mt) {
                uint32_t ao = arow[mt] + (uint32_t)((cix ^ axor[mt]) << 4);
                LDSM4(ah + mt * 4, sA + ao);
            }
            #pragma unroll
            for (int np = 0; np < 4; ++np) {
                uint32_t bo = brow[np] + (uint32_t)((cix ^ bxor[np]) << 4);
                LDSM4(bh + np * 4, sB + bo);
            }
            #pragma unroll
            for (int np = 0; np < 4; ++np)
                #pragma unroll
                for (int mt = 0; mt < 2; ++mt)
                    #pragma unroll
                    for (int hf = 0; hf < 2; ++hf)
                        MMA_F16(acc[mt][np * 2 + hf], ah + mt * 4,
                                bh[np * 4 + hf], bh[np * 4 + 2 + hf]);
        }
    }

    // Epilogue
    if (mode == 0) {
        const int ncol0 = n0 + wn * 64;
        const int which = ncol0 >> 10;
        const int hh    = (ncol0 & 1023) >> 6;
        __half* dst = (which == 0) ? g_q : ((which == 1) ? g_k : g_v);
        const float qs = (which == 0) ? 0.125f : 1.0f;
        #pragma unroll
        for (int mt = 0; mt < 2; ++mt) {
            const int rg0 = m0 + wm * 32 + mt * 16 + (lane >> 2);
            const int bb  = rg0 >> 11;
            const int t0  = rg0 & 2047;
            const size_t rbase = (((size_t)bb * Hn + hh) * Tdim + t0) * HDd;
            #pragma unroll
            for (int nt = 0; nt < 8; ++nt) {
                const int d = nt * 8 + (lane & 3) * 2;
                const float2 bv = *(const float2*)&bias[ncol0 + d];
                *(uint32_t*)&dst[rbase + d] =
                    pack2h((acc[mt][nt][0] + bv.x) * qs, (acc[mt][nt][1] + bv.y) * qs);
                *(uint32_t*)&dst[rbase + 8 * HDd + d] =
                    pack2h((acc[mt][nt][2] + bv.x) * qs, (acc[mt][nt][3] + bv.y) * qs);
            }
        }
    } else {
        #pragma unroll
        for (int mt = 0; mt < 2; ++mt) {
            const int rg0 = m0 + wm * 32 + mt * 16 + (lane >> 2);
            #pragma unroll
            for (int nt = 0; nt < 8; ++nt) {
                const int ncol = n0 + wn * 64 + nt * 8 + (lane & 3) * 2;
                const float2 bv = *(const float2*)&bias[ncol];
                float2 v0, v1;
                v0.x = acc[mt][nt][0] + bv.x;
                v0.y = acc[mt][nt][1] + bv.y;
                v1.x = acc[mt][nt][2] + bv.x;
                v1.y = acc[mt][nt][3] + bv.y;
                size_t base = (size_t)rg0 * Cdim + ncol;
                *(float2*)&out[base]            = v0;
                *(float2*)&out[base + 8 * Cdim] = v1;
            }
        }
    }
}

// ---------------------------------------------------------------------------
// mma.sync causal flash attention, single fp16 for QK^T and PV.
// BQ=128 (8 warps x 16 rows), BKV=64, HD=64. Double-buffered K/V cp.async.
// smem: Q @ 0 (18432); stage s: K @ 18432+s*18432, V @ +9216.
// ---------------------------------------------------------------------------
#define ARS 144                      // row stride bytes
#define AQ  0
#define AKV0 18432
#define KVSTG 18432                  // per-stage (K 9216 + V 9216)
#define ASMEM (AKV0 + 2 * KVSTG)     // 55296

__global__ __launch_bounds__(256, 2) void attn_mma_kernel() {
    extern __shared__ __align__(16) char asmem[];
    const int tid = threadIdx.x;
    const int lane = tid & 31;
    const int w = tid >> 5;
    const int qt = gridDim.x - 1 - blockIdx.x;   // heavy tiles first
    const int bh = blockIdx.y;

    const uint32_t uS = smem_u32(asmem);
    const size_t hbase = (size_t)bh * Tdim * HDd;
    const __half* qq = g_q + hbase;
    const __half* kk = g_k + hbase;
    const __half* vv = g_v + hbase;

    auto issue_kv = [&](int kt) {
        const uint32_t sb = uS + AKV0 + (uint32_t)(kt & 1) * KVSTG;
        #pragma unroll
        for (int it = 0; it < 2; ++it) {
            int idx = tid + it * 256;
            int row = idx >> 3, c = idx & 7;
            uint32_t dst = row * ARS + c * 16;
            size_t src = (size_t)(kt * 64 + row) * HDd + c * 8;
            CP_ASYNC16(sb + dst,        kk + src);
            CP_ASYNC16(sb + 9216 + dst, vv + src);
        }
        CP_COMMIT();
    };

    // Q tile load (committed with KV stage 0)
    #pragma unroll
    for (int it = 0; it < 4; ++it) {
        int idx = tid + it * 256;
        int row = idx >> 3, c = idx & 7;
        uint32_t dst = row * ARS + c * 16;
        size_t src = (size_t)(qt * 128 + row) * HDd + c * 8;
        CP_ASYNC16(uS + AQ + dst, qq + src);
    }
    issue_kv(0);

    const int r4 = lane >> 2;
    const int c2 = (lane & 3) * 2;
    float m0 = -1e30f, m1 = -1e30f, l0 = 0.f, l1 = 0.f;
    float O[8][4] = {};

    const int nkt = 2 * qt + 2;
    for (int kt = 0; kt < nkt; ++kt) {
        const bool more = (kt + 1 < nkt);
        if (more) issue_kv(kt + 1);
        if (more) { asm volatile("cp.async.wait_group 1;"); }
        else      { asm volatile("cp.async.wait_group 0;"); }
        __syncthreads();

        const uint32_t kvb = uS + AKV0 + (uint32_t)(kt & 1) * KVSTG;
        const uint32_t uK = kvb, uV = kvb + 9216;

        // ---- S = Q K^T (single fp16) ----
        float S[8][4] = {};
        #pragma unroll
        for (int k16 = 0; k16 < 4; ++k16) {
            const uint32_t qoff =
                (uint32_t)((w * 16 + (lane & 15)) * ARS + (lane >> 4) * 16 + k16 * 32);
            const uint32_t kfrag =
                (uint32_t)((lane & 15) * ARS + (lane >> 4) * 16 + k16 * 32);
            uint32_t aq[4], bk[16];
            LDSM4(aq, uS + AQ + qoff);
            #pragma unroll
            for (int kp = 0; kp < 4; ++kp)
                LDSM4(bk + kp * 4, uK + kfrag + (uint32_t)(kp * 16) * ARS);
            #pragma unroll
            for (int kp = 0; kp < 4; ++kp)
                #pragma unroll
                for (int hf = 0; hf < 2; ++hf)
                    MMA_F16(S[kp * 2 + hf], aq, bk[kp * 4 + hf], bk[kp * 4 + 2 + hf]);
        }

        // ---- causal mask ----
        const int row0 = qt * 128 + w * 16 + r4;
        if (kt * 64 + 63 > qt * 128 + w * 16) {
            #pragma unroll
            for (int j = 0; j < 8; ++j) {
                const int cb = kt * 64 + j * 8 + c2;
                if (cb     > row0)     S[j][0] = -1e30f;
                if (cb + 1 > row0)     S[j][1] = -1e30f;
                if (cb     > row0 + 8) S[j][2] = -1e30f;
                if (cb + 1 > row0 + 8) S[j][3] = -1e30f;
            }
        }

        // ---- online softmax on fragments ----
        float mt0 = -1e30f, mt1 = -1e30f;
        #pragma unroll
        for (int j = 0; j < 8; ++j) {
            mt0 = fmaxf(mt0, fmaxf(S[j][0], S[j][1]));
            mt1 = fmaxf(mt1, fmaxf(S[j][2], S[j][3]));
        }
        mt0 = fmaxf(mt0, __shfl_xor_sync(0xffffffffu, mt0, 1));
        mt0 = fmaxf(mt0, __shfl_xor_sync(0xffffffffu, mt0, 2));
        mt1 = fmaxf(mt1, __shfl_xor_sync(0xffffffffu, mt1, 1));
        mt1 = fmaxf(mt1, __shfl_xor_sync(0xffffffffu, mt1, 2));
        const float mn0 = fmaxf(m0, mt0);
        const float mn1 = fmaxf(m1, mt1);
        const float sf0 = __expf(m0 - mn0);
        const float sf1 = __expf(m1 - mn1);
        m0 = mn0; m1 = mn1;

        float rs0 = 0.f, rs1 = 0.f;
        #pragma unroll
        for (int j = 0; j < 8; ++j) {
            S[j][0] = __expf(S[j][0] - m0);
            S[j][1] = __expf(S[j][1] - m0);
            S[j][2] = __expf(S[j][2] - m1);
            S[j][3] = __expf(S[j][3] - m1);
            rs0 += S[j][0] + S[j][1];
            rs1 += S[j][2] + S[j][3];
        }
        rs0 += __shfl_xor_sync(0xffffffffu, rs0, 1);
        rs0 += __shfl_xor_sync(0xffffffffu, rs0, 2);
        rs1 += __shfl_xor_sync(0xffffffffu, rs1, 1);
        rs1 += __shfl_xor_sync(0xffffffffu, rs1, 2);
        l0 = l0 * sf0 + rs0;
        l1 = l1 * sf1 + rs1;
        #pragma unroll
        for (int j = 0; j < 8; ++j) {
            O[j][0] *= sf0; O[j][1] *= sf0;
            O[j][2] *= sf1; O[j][3] *= sf1;
        }

        // ---- O += P V (single fp16 P, single V) ----
        #pragma unroll
        for (int s = 0; s < 4; ++s) {
            uint32_t ph[4];
            ph[0] = pack2h(S[2 * s][0],     S[2 * s][1]);
            ph[1] = pack2h(S[2 * s][2],     S[2 * s][3]);
            ph[2] = pack2h(S[2 * s + 1][0], S[2 * s + 1][1]);
            ph[3] = pack2h(S[2 * s + 1][2], S[2 * s + 1][3]);
            const uint32_t vrow =
                (uint32_t)((s * 16 + (lane & 7) + ((lane >> 3) & 1) * 8) * ARS
                           + (lane >> 4) * 16);
            uint32_t bv[16];
            #pragma unroll
            for (int np = 0; np < 4; ++np)
                LDSM4T(bv + np * 4, uV + vrow + np * 32);
            #pragma unroll
            for (int np = 0; np < 4; ++np) {
                MMA_F16(O[np * 2],     ph, bv[np * 4],     bv[np * 4 + 1]);
                MMA_F16(O[np * 2 + 1], ph, bv[np * 4 + 2], bv[np * 4 + 3]);
            }
        }
        __syncthreads();
    }

    // ---- normalize + write y (fp16 single for proj) ----
    const float inv0 = 1.f / l0, inv1 = 1.f / l1;
    const int b = bh >> 4, h = bh & 15;
    const int rg0 = b * Tdim + qt * 128 + w * 16 + r4;
    const size_t base0 = (size_t)rg0 * Cdim + h * HDd;
    #pragma unroll
    for (int j = 0; j < 8; ++j) {
        const int d = j * 8 + c2;
        *(uint32_t*)&g_y[base0 + d] = pack2h(O[j][0] * inv0, O[j][1] * inv0);
        *(uint32_t*)&g_y[base0 + 8 * Cdim + d] = pack2h(O[j][2] * inv1, O[j][3] * inv1);
    }
}

// ---------------------------------------------------------------------------
extern "C" void kernel_launch(void* const* d_in, const int* in_sizes, int n_in,
                              void* d_out, int out_size) {
    const float* x      = (const float*)d_in[0];
    const float* w_attn = (const float*)d_in[1];
    const float* b_attn = (const float*)d_in[2];
    const float* w_proj = (const float*)d_in[3];
    const float* b_proj = (const float*)d_in[4];
    float* out = (float*)d_out;

    static bool attr_set = false;
    if (!attr_set) {
        cudaFuncSetAttribute(gemm_f16_kernel,
                             cudaFuncAttributeMaxDynamicSharedMemorySize, GSMEM);
        cudaFuncSetAttribute(attn_mma_kernel,
                             cudaFuncAttributeMaxDynamicSharedMemorySize, ASMEM);
        attr_set = true;
    }

    __half *xp, *wa, *wp, *yp;
    cudaGetSymbolAddress((void**)&xp, g_x);
    cudaGetSymbolAddress((void**)&wa, g_wa);
    cudaGetSymbolAddress((void**)&wp, g_wp);
    cudaGetSymbolAddress((void**)&yp, g_y);

    // Prep: convert x to fp16, transpose weights to fp16 [N][K]
    prep_x_kernel<<<Mrows * Cdim / (256 * 4), 256>>>(x);
    {
        dim3 ga(N3 / 32, Cdim / 32);
        prep_w_kernel<<<ga, 256>>>(w_attn, wa, Cdim, N3);
        dim3 gp(Cdim / 32, Cdim / 32);
        prep_w_kernel<<<gp, 256>>>(w_proj, wp, Cdim, Cdim);
    }

    // QKV GEMM -> q (x0.125) / k / v fp16 head-major
    dim3 g1(N3 / 128, Mrows / 128);     // 24 x 32
    gemm_f16_kernel<<<g1, 256, GSMEM>>>(xp, wa, b_attn, nullptr, 0);

    // Attention (tensor-core, single fp16, double-buffered K/V)
    dim3 g2(Tdim / 128, Bdim * Hn);     // 16 x 32
    attn_mma_kernel<<<g2, 256, ASMEM>>>();

    // Proj GEMM
    dim3 g3(Cdim / 128, Mrows / 128);   // 8 x 32
    gemm_f16_kernel<<<g3, 256, GSMEM>>>(yp, wp, b_proj, out, 1);
}

// round 11
// speedup vs baseline: 1.7029x; 1.0496x over previous
#include <cuda_runtime.h>
#include <cuda_fp16.h>
#include <cstdint>

// Problem constants
#define Bdim 2
#define Tdim 2048
#define Cdim 1024
#define Hn   16
#define HDd  64
#define Mrows (Bdim * Tdim)   // 4096
#define N3    (3 * Cdim)      // 3072

// ---------------------------------------------------------------------------
// Scratch (__device__ globals; allocation-free rule) — all single fp16
// ---------------------------------------------------------------------------
__device__ __half g_x [Mrows * Cdim];
__device__ __half g_wa[N3 * Cdim];        // [N=3072][K=1024]
__device__ __half g_wp[Cdim * Cdim];      // [N=1024][K=1024]
__device__ __half g_y [Mrows * Cdim];     // attn output, [B*T][C]

// q (pre-scaled by 0.125*log2e), k, v. Head-major [B*H][T][HD]
__device__ __half g_q[Bdim * Hn * Tdim * HDd];
__device__ __half g_k[Bdim * Hn * Tdim * HDd];
__device__ __half g_v[Bdim * Hn * Tdim * HDd];

// ---------------------------------------------------------------------------
// PTX helpers (plain sm_103-safe)
// ---------------------------------------------------------------------------
__device__ __forceinline__ uint32_t smem_u32(const void* p) {
    uint32_t a;
    asm("{ .reg .u64 t; cvta.to.shared.u64 t, %1; cvt.u32.u64 %0, t; }"
        : "=r"(a) : "l"(p));
    return a;
}

#define LDSM4(r, addr) \
    asm volatile("ldmatrix.sync.aligned.m8n8.x4.shared.b16 {%0,%1,%2,%3}, [%4];" \
        : "=r"((r)[0]), "=r"((r)[1]), "=r"((r)[2]), "=r"((r)[3]) : "r"(addr))

#define LDSM4T(r, addr) \
    asm volatile("ldmatrix.sync.aligned.m8n8.x4.trans.shared.b16 {%0,%1,%2,%3}, [%4];" \
        : "=r"((r)[0]), "=r"((r)[1]), "=r"((r)[2]), "=r"((r)[3]) : "r"(addr))

#define MMA_F16(c, a, b0, b1) \
    asm volatile("mma.sync.aligned.m16n8k16.row.col.f32.f16.f16.f32 " \
        "{%0,%1,%2,%3}, {%4,%5,%6,%7}, {%8,%9}, {%0,%1,%2,%3};" \
        : "+f"((c)[0]), "+f"((c)[1]), "+f"((c)[2]), "+f"((c)[3]) \
        : "r"((a)[0]), "r"((a)[1]), "r"((a)[2]), "r"((a)[3]), "r"(b0), "r"(b1))

#define CP_ASYNC16(dst, src) \
    asm volatile("cp.async.cg.shared.global [%0], [%1], 16;" :: "r"(dst), "l"(src))
#define CP_COMMIT() asm volatile("cp.async.commit_group;")

__device__ __forceinline__ uint32_t pack2h(float v0, float v1) {
    __half2 h(__float2half_rn(v0), __float2half_rn(v1));
    return *(uint32_t*)&h;
}

// ---------------------------------------------------------------------------
// Prep kernels
// ---------------------------------------------------------------------------
__global__ __launch_bounds__(256) void prep_x_kernel(const float* __restrict__ x) {
    int i = (blockIdx.x * 256 + threadIdx.x) * 4;
    float4 v = *(const float4*)&x[i];
    *(uint32_t*)&g_x[i]     = pack2h(v.x, v.y);
    *(uint32_t*)&g_x[i + 2] = pack2h(v.z, v.w);
}

// Transpose W [K, N] -> Wt [N, K] fp16 single
__global__ __launch_bounds__(256) void prep_w_kernel(
    const float* __restrict__ W, __half* __restrict__ Wt, int K, int N) {
    __shared__ float tile[32][33];
    int n0 = blockIdx.x * 32, k0 = blockIdx.y * 32;
    int tx = threadIdx.x & 31, ty = threadIdx.x >> 5;   // 32 x 8
    #pragma unroll
    for (int r = 0; r < 32; r += 8)
        tile[ty + r][tx] = W[(size_t)(k0 + ty + r) * N + n0 + tx];
    __syncthreads();
    #pragma unroll
    for (int r = 0; r < 32; r += 8) {
        float v = tile[tx][ty + r];
        Wt[(size_t)(n0 + ty + r) * K + k0 + tx] = __float2half_rn(v);
    }
}

// ---------------------------------------------------------------------------
// mma.sync fp16 GEMM (unchanged from R10): D = A * B^T + bias
// ---------------------------------------------------------------------------
#define GARR8  8192
#define GSTG   (2 * GARR8)          // 16384 per stage (A, B)
#define GSMEM  (3 * GSTG)           // 49152
#define QSCALE 0.1803368801111204f  // 0.125 * log2(e)

__device__ __forceinline__ uint32_t pk_off(int m, int c) {
    return (uint32_t)((m >> 1) * 128 + (m & 1) * 64 + ((c ^ ((m >> 1) & 3)) << 4));
}

__global__ __launch_bounds__(256, 2)
void gemm_f16_kernel(const __half* __restrict__ A,
                     const __half* __restrict__ Bw,
                     const float* __restrict__ bias,
                     float* __restrict__ out, int mode) {
    extern __shared__ __align__(16) char dynsm[];

    const int tid  = threadIdx.x;
    const int lane = tid & 31;
    const int wid  = tid >> 5;
    const int wm   = wid & 3;
    const int wn   = wid >> 2;
    const int n0 = blockIdx.x * 128;
    const int m0 = blockIdx.y * 128;

    const uint32_t uS = smem_u32(dynsm);

    float acc[2][8][4] = {};

    auto issue = [&](int ch) {
        const uint32_t sb = uS + (uint32_t)(ch % 3) * GSTG;
        const int k0 = ch * 32;
        #pragma unroll
        for (int it = 0; it < 2; ++it) {
            int idx = tid + it * 256;
            int m = idx >> 2;
            int c = idx & 3;
            uint32_t so = pk_off(m, c);
            size_t ga = (size_t)(m0 + m) * Cdim + k0 + c * 8;
            size_t gb = (size_t)(n0 + m) * Cdim + k0 + c * 8;
            CP_ASYNC16(sb + so,         A + ga);
            CP_ASYNC16(sb + GARR8 + so, Bw + gb);
        }
        CP_COMMIT();
    };

    uint32_t arow[2], axor[2], brow[4], bxor[4];
    #pragma unroll
    for (int mt = 0; mt < 2; ++mt) {
        int m = wm * 32 + mt * 16 + (lane & 15);
        arow[mt] = (uint32_t)((m >> 1) * 128 + (m & 1) * 64);
        axor[mt] = (uint32_t)((m >> 1) & 3);
    }
    #pragma unroll
    for (int np = 0; np < 4; ++np) {
        int n = wn * 64 + np * 16 + (lane & 15);
        brow[np] = (uint32_t)((n >> 1) * 128 + (n & 1) * 64);
        bxor[np] = (uint32_t)((n >> 1) & 3);
    }
    const int chalf = lane >> 4;

    const int NCH = Cdim / 32;
    issue(0);
    issue(1);

    for (int ch = 0; ch < NCH; ++ch) {
        if (ch + 1 < NCH) { asm volatile("cp.async.wait_group 1;"); }
        else              { asm volatile("cp.async.wait_group 0;"); }
        __syncthreads();
        if (ch + 2 < NCH) issue(ch + 2);

        const uint32_t sb = uS + (uint32_t)(ch % 3) * GSTG;
        const uint32_t sA = sb, sB = sb + GARR8;

        #pragma unroll
        for (int kk = 0; kk < 2; ++kk) {
            const int cix = kk * 2 + chalf;
            uint32_t ah[8], bh[16];
            #pragma unroll
            for (int mt = 0; mt < 2; ++mt) {
                uint32_t ao = arow[mt] + (uint32_t)((cix ^ axor[mt]) << 4);
                LDSM4(ah + mt * 4, sA + ao);
            }
            #pragma unroll
            for (int np = 0; np < 4; ++np) {
                uint32_t bo = brow[np] + (uint32_t)((cix ^ bxor[np]) << 4);
                LDSM4(bh + np * 4, sB + bo);
            }
            #pragma unroll
            for (int np = 0; np < 4; ++np)
                #pragma unroll
                for (int mt = 0; mt < 2; ++mt)
                    #pragma unroll
                    for (int hf = 0; hf < 2; ++hf)
                        MMA_F16(acc[mt][np * 2 + hf], ah + mt * 4,
                                bh[np * 4 + hf], bh[np * 4 + 2 + hf]);
        }
    }

    if (mode == 0) {
        const int ncol0 = n0 + wn * 64;
        const int which = ncol0 >> 10;
        const int hh    = (ncol0 & 1023) >> 6;
        __half* dst = (which == 0) ? g_q : ((which == 1) ? g_k : g_v);
        const float qs = (which == 0) ? QSCALE : 1.0f;
        #pragma unroll
        for (int mt = 0; mt < 2; ++mt) {
            const int rg0 = m0 + wm * 32 + mt * 16 + (lane >> 2);
            const int bb  = rg0 >> 11;
            const int t0  = rg0 & 2047;
            const size_t rbase = (((size_t)bb * Hn + hh) * Tdim + t0) * HDd;
            #pragma unroll
            for (int nt = 0; nt < 8; ++nt) {
                const int d = nt * 8 + (lane & 3) * 2;
                const float2 bv = *(const float2*)&bias[ncol0 + d];
                *(uint32_t*)&dst[rbase + d] =
                    pack2h((acc[mt][nt][0] + bv.x) * qs, (acc[mt][nt][1] + bv.y) * qs);
                *(uint32_t*)&dst[rbase + 8 * HDd + d] =
                    pack2h((acc[mt][nt][2] + bv.x) * qs, (acc[mt][nt][3] + bv.y) * qs);
            }
        }
    } else {
        #pragma unroll
        for (int mt = 0; mt < 2; ++mt) {
            const int rg0 = m0 + wm * 32 + mt * 16 + (lane >> 2);
            #pragma unroll
            for (int nt = 0; nt < 8; ++nt) {
                const int ncol = n0 + wn * 64 + nt * 8 + (lane & 3) * 2;
                const float2 bv = *(const float2*)&bias[ncol];
                float2 v0, v1;
                v0.x = acc[mt][nt][0] + bv.x;
                v0.y = acc[mt][nt][1] + bv.y;
                v1.x = acc[mt][nt][2] + bv.x;
                v1.y = acc[mt][nt][3] + bv.y;
                size_t base = (size_t)rg0 * Cdim + ncol;
                *(float2*)&out[base]            = v0;
                *(float2*)&out[base + 8 * Cdim] = v1;
            }
        }
    }
}

// ---------------------------------------------------------------------------
// mma.sync causal flash attention v2: 4 warps x 32 q-rows, BQ=128, BKV=64.
// Q fragments cached in registers; K/V read by only 4 warps -> LDSM-light.
// Scores in log2 domain (q pre-scaled by 0.125*log2e), exp2f softmax.
// ---------------------------------------------------------------------------
#define ARS 144                      // row stride bytes
#define AQ  0
#define AKV0 18432
#define KVSTG 18432                  // per-stage (K 9216 + V 9216)
#define ASMEM (AKV0 + 2 * KVSTG)     // 55296

__global__ __launch_bounds__(128, 2) void attn_mma_kernel() {
    extern __shared__ __align__(16) char asmem[];
    const int tid = threadIdx.x;
    const int lane = tid & 31;
    const int w = tid >> 5;                       // 0..3, owns 32 q rows
    const int qt = gridDim.x - 1 - blockIdx.x;    // heavy tiles first
    const int bh = blockIdx.y;

    const uint32_t uS = smem_u32(asmem);
    const size_t hbase = (size_t)bh * Tdim * HDd;
    const __half* qq = g_q + hbase;
    const __half* kk = g_k + hbase;
    const __half* vv = g_v + hbase;

    auto issue_kv = [&](int kt) {
        const uint32_t sb = uS + AKV0 + (uint32_t)(kt & 1) * KVSTG;
        #pragma unroll
        for (int it = 0; it < 4; ++it) {
            int idx = tid + it * 128;
            int row = idx >> 3, c = idx & 7;
            uint32_t dst = row * ARS + c * 16;
            size_t src = (size_t)(kt * 64 + row) * HDd + c * 8;
            CP_ASYNC16(sb + dst,        kk + src);
            CP_ASYNC16(sb + 9216 + dst, vv + src);
        }
        CP_COMMIT();
    };

    // Q tile load (committed together with KV stage 0)
    #pragma unroll
    for (int it = 0; it < 8; ++it) {
        int idx = tid + it * 128;
        int row = idx >> 3, c = idx & 7;
        uint32_t dst = row * ARS + c * 16;
        size_t src = (size_t)(qt * 128 + row) * HDd + c * 8;
        CP_ASYNC16(uS + AQ + dst, qq + src);
    }
    issue_kv(0);

    const int r4 = lane >> 2;
    const int c2 = (lane & 3) * 2;
    float m[4], l[4];
    #pragma unroll
    for (int i = 0; i < 4; ++i) { m[i] = -1e30f; l[i] = 0.f; }
    float O[2][8][4] = {};
    uint32_t aq[2][4][4];          // Q fragments cached: [mt][k16][4]

    const int nkt = 2 * qt + 2;
    for (int kt = 0; kt < nkt; ++kt) {
        const bool more = (kt + 1 < nkt);
        if (more) issue_kv(kt + 1);
        if (more) { asm volatile("cp.async.wait_group 1;"); }
        else      { asm volatile("cp.async.wait_group 0;"); }
        __syncthreads();

        if (kt == 0) {
            // one-time Q fragment load into registers
            #pragma unroll
            for (int mt = 0; mt < 2; ++mt)
                #pragma unroll
                for (int k16 = 0; k16 < 4; ++k16) {
                    uint32_t qoff = (uint32_t)((w * 32 + mt * 16 + (lane & 15)) * ARS
                                               + (lane >> 4) * 16 + k16 * 32);
                    LDSM4(aq[mt][k16], uS + AQ + qoff);
                }
        }

        const uint32_t kvb = uS + AKV0 + (uint32_t)(kt & 1) * KVSTG;
        const uint32_t uK = kvb, uV = kvb + 9216;

        // ---- S = Q K^T (single fp16, Q from registers) ----
        float S[2][8][4] = {};
        #pragma unroll
        for (int k16 = 0; k16 < 4; ++k16) {
            const uint32_t kfrag =
                (uint32_t)((lane & 15) * ARS + (lane >> 4) * 16 + k16 * 32);
            uint32_t bk[16];
            #pragma unroll
            for (int kp = 0; kp < 4; ++kp)
                LDSM4(bk + kp * 4, uK + kfrag + (uint32_t)(kp * 16) * ARS);
            #pragma unroll
            for (int kp = 0; kp < 4; ++kp)
                #pragma unroll
                for (int mt = 0; mt < 2; ++mt)
                    #pragma unroll
                    for (int hf = 0; hf < 2; ++hf)
                        MMA_F16(S[mt][kp * 2 + hf], aq[mt][k16],
                                bk[kp * 4 + hf], bk[kp * 4 + 2 + hf]);
        }

        // ---- causal mask ----
        if (kt * 64 + 63 > qt * 128 + w * 32) {
            #pragma unroll
            for (int mt = 0; mt < 2; ++mt) {
                const int row0 = qt * 128 + w * 32 + mt * 16 + r4;
                #pragma unroll
                for (int j = 0; j < 8; ++j) {
                    const int cb = kt * 64 + j * 8 + c2;
                    if (cb     > row0)     S[mt][j][0] = -1e30f;
                    if (cb + 1 > row0)     S[mt][j][1] = -1e30f;
                    if (cb     > row0 + 8) S[mt][j][2] = -1e30f;
                    if (cb + 1 > row0 + 8) S[mt][j][3] = -1e30f;
                }
            }
        }

        // ---- online softmax (log2 domain, exp2f) ----
        #pragma unroll
        for (int mt = 0; mt < 2; ++mt) {
            float mt0 = -1e30f, mt1 = -1e30f;
            #pragma unroll
            for (int j = 0; j < 8; ++j) {
                mt0 = fmaxf(mt0, fmaxf(S[mt][j][0], S[mt][j][1]));
                mt1 = fmaxf(mt1, fmaxf(S[mt][j][2], S[mt][j][3]));
            }
            mt0 = fmaxf(mt0, __shfl_xor_sync(0xffffffffu, mt0, 1));
            mt0 = fmaxf(mt0, __shfl_xor_sync(0xffffffffu, mt0, 2));
            mt1 = fmaxf(mt1, __shfl_xor_sync(0xffffffffu, mt1, 1));
            mt1 = fmaxf(mt1, __shfl_xor_sync(0xffffffffu, mt1, 2));
            const float mn0 = fmaxf(m[mt * 2],     mt0);
            const float mn1 = fmaxf(m[mt * 2 + 1], mt1);
            const float sf0 = exp2f(m[mt * 2]     - mn0);
            const float sf1 = exp2f(m[mt * 2 + 1] - mn1);
            m[mt * 2] = mn0; m[mt * 2 + 1] = mn1;

            float rs0 = 0.f, rs1 = 0.f;
            #pragma unroll
            for (int j = 0; j < 8; ++j) {
                S[mt][j][0] = exp2f(S[mt][j][0] - mn0);
                S[mt][j][1] = exp2f(S[mt][j][1] - mn0);
                S[mt][j][2] = exp2f(S[mt][j][2] - mn1);
                S[mt][j][3] = exp2f(S[mt][j][3] - mn1);
                rs0 += S[mt][j][0] + S[mt][j][1];
                rs1 += S[mt][j][2] + S[mt][j][3];
            }
            rs0 += __shfl_xor_sync(0xffffffffu, rs0, 1);
            rs0 += __shfl_xor_sync(0xffffffffu, rs0, 2);
            rs1 += __shfl_xor_sync(0xffffffffu, rs1, 1);
            rs1 += __shfl_xor_sync(0xffffffffu, rs1, 2);
            l[mt * 2]     = l[mt * 2]     * sf0 + rs0;
            l[mt * 2 + 1] = l[mt * 2 + 1] * sf1 + rs1;
            #pragma unroll
            for (int j = 0; j < 8; ++j) {
                O[mt][j][0] *= sf0; O[mt][j][1] *= sf0;
                O[mt][j][2] *= sf1; O[mt][j][3] *= sf1;
            }
        }

        // ---- O += P V (single fp16) ----
        #pragma unroll
        for (int s = 0; s < 4; ++s) {
            const uint32_t vrow =
                (uint32_t)((s * 16 + (lane & 7) + ((lane >> 3) & 1) * 8) * ARS
                           + (lane >> 4) * 16);
            uint32_t bv[16];
            #pragma unroll
            for (int np = 0; np < 4; ++np)
                LDSM4T(bv + np * 4, uV + vrow + np * 32);
            #pragma unroll
            for (int mt = 0; mt < 2; ++mt) {
                uint32_t ph[4];
                ph[0] = pack2h(S[mt][2 * s][0],     S[mt][2 * s][1]);
                ph[1] = pack2h(S[mt][2 * s][2],     S[mt][2 * s][3]);
                ph[2] = pack2h(S[mt][2 * s + 1][0], S[mt][2 * s + 1][1]);
                ph[3] = pack2h(S[mt][2 * s + 1][2], S[mt][2 * s + 1][3]);
                #pragma unroll
                for (int np = 0; np < 4; ++np) {
                    MMA_F16(O[mt][np * 2],     ph, bv[np * 4],     bv[np * 4 + 1]);
                    MMA_F16(O[mt][np * 2 + 1], ph, bv[np * 4 + 2], bv[np * 4 + 3]);
                }
            }
        }
        __syncthreads();
    }

    // ---- normalize + write y (fp16 single for proj) ----
    const int b = bh >> 4, h = bh & 15;
    #pragma unroll
    for (int mt = 0; mt < 2; ++mt) {
        const float inv0 = 1.f / l[mt * 2];
        const float inv1 = 1.f / l[mt * 2 + 1];
        const int rg0 = b * Tdim + qt * 128 + w * 32 + mt * 16 + r4;
        const size_t base0 = (size_t)rg0 * Cdim + h * HDd;
        #pragma unroll
        for (int j = 0; j < 8; ++j) {
            const int d = j * 8 + c2;
            *(uint32_t*)&g_y[base0 + d] =
                pack2h(O[mt][j][0] * inv0, O[mt][j][1] * inv0);
            *(uint32_t*)&g_y[base0 + 8 * Cdim + d] =
                pack2h(O[mt][j][2] * inv1, O[mt][j][3] * inv1);
        }
    }
}

// ---------------------------------------------------------------------------
extern "C" void kernel_launch(void* const* d_in, const int* in_sizes, int n_in,
                              void* d_out, int out_size) {
    const float* x      = (const float*)d_in[0];
    const float* w_attn = (const float*)d_in[1];
    const float* b_attn = (const float*)d_in[2];
    const float* w_proj = (const float*)d_in[3];
    const float* b_proj = (const float*)d_in[4];
    float* out = (float*)d_out;

    static bool attr_set = false;
    if (!attr_set) {
        cudaFuncSetAttribute(gemm_f16_kernel,
                             cudaFuncAttributeMaxDynamicSharedMemorySize, GSMEM);
        cudaFuncSetAttribute(attn_mma_kernel,
                             cudaFuncAttributeMaxDynamicSharedMemorySize, ASMEM);
        attr_set = true;
    }

    __half *xp, *wa, *wp, *yp;
    cudaGetSymbolAddress((void**)&xp, g_x);
    cudaGetSymbolAddress((void**)&wa, g_wa);
    cudaGetSymbolAddress((void**)&wp, g_wp);
    cudaGetSymbolAddress((void**)&yp, g_y);

    // Prep: convert x to fp16, transpose weights to fp16 [N][K]
    prep_x_kernel<<<Mrows * Cdim / (256 * 4), 256>>>(x);
    {
        dim3 ga(N3 / 32, Cdim / 32);
        prep_w_kernel<<<ga, 256>>>(w_attn, wa, Cdim, N3);
        dim3 gp(Cdim / 32, Cdim / 32);
        prep_w_kernel<<<gp, 256>>>(w_proj, wp, Cdim, Cdim);
    }

    // QKV GEMM -> q (x0.125*log2e) / k / v fp16 head-major
    dim3 g1(N3 / 128, Mrows / 128);     // 24 x 32
    gemm_f16_kernel<<<g1, 256, GSMEM>>>(xp, wa, b_attn, nullptr, 0);

    // Attention (tensor-core, 4-warp CTAs, Q cached in regs, exp2 softmax)
    dim3 g2(Tdim / 128, Bdim * Hn);     // 16 x 32, 128-thread CTAs
    attn_mma_kernel<<<g2, 128, ASMEM>>>();

    // Proj GEMM
    dim3 g3(Cdim / 128, Mrows / 128);   // 8 x 32
    gemm_f16_kernel<<<g3, 256, GSMEM>>>(yp, wp, b_proj, out, 1);
}

// round 12
// speedup vs baseline: 1.7396x; 1.0216x over previous
#include <cuda_runtime.h>
#include <cuda_fp16.h>
#include <cstdint>

// Problem constants
#define Bdim 2
#define Tdim 2048
#define Cdim 1024
#define Hn   16
#define HDd  64
#define Mrows (Bdim * Tdim)   // 4096
#define N3    (3 * Cdim)      // 3072

// ---------------------------------------------------------------------------
// Scratch (__device__ globals; allocation-free rule) — all single fp16
// ---------------------------------------------------------------------------
__device__ __half g_x [Mrows * Cdim];
__device__ __half g_wa[N3 * Cdim];        // [N=3072][K=1024]
__device__ __half g_wp[Cdim * Cdim];      // [N=1024][K=1024]
__device__ __half g_y [Mrows * Cdim];     // attn output, [B*T][C]

// q (pre-scaled by 0.125*log2e), k, v. Head-major [B*H][T][HD]
__device__ __half g_q[Bdim * Hn * Tdim * HDd];
__device__ __half g_k[Bdim * Hn * Tdim * HDd];
__device__ __half g_v[Bdim * Hn * Tdim * HDd];

// ---------------------------------------------------------------------------
// PTX helpers (plain sm_103-safe)
// ---------------------------------------------------------------------------
__device__ __forceinline__ uint32_t smem_u32(const void* p) {
    uint32_t a;
    asm("{ .reg .u64 t; cvta.to.shared.u64 t, %1; cvt.u32.u64 %0, t; }"
        : "=r"(a) : "l"(p));
    return a;
}

#define LDSM4(r, addr) \
    asm volatile("ldmatrix.sync.aligned.m8n8.x4.shared.b16 {%0,%1,%2,%3}, [%4];" \
        : "=r"((r)[0]), "=r"((r)[1]), "=r"((r)[2]), "=r"((r)[3]) : "r"(addr))

#define LDSM4T(r, addr) \
    asm volatile("ldmatrix.sync.aligned.m8n8.x4.trans.shared.b16 {%0,%1,%2,%3}, [%4];" \
        : "=r"((r)[0]), "=r"((r)[1]), "=r"((r)[2]), "=r"((r)[3]) : "r"(addr))

#define MMA_F16(c, a, b0, b1) \
    asm volatile("mma.sync.aligned.m16n8k16.row.col.f32.f16.f16.f32 " \
        "{%0,%1,%2,%3}, {%4,%5,%6,%7}, {%8,%9}, {%0,%1,%2,%3};" \
        : "+f"((c)[0]), "+f"((c)[1]), "+f"((c)[2]), "+f"((c)[3]) \
        : "r"((a)[0]), "r"((a)[1]), "r"((a)[2]), "r"((a)[3]), "r"(b0), "r"(b1))

#define CP_ASYNC16(dst, src) \
    asm volatile("cp.async.cg.shared.global [%0], [%1], 16;" :: "r"(dst), "l"(src))
#define CP_COMMIT() asm volatile("cp.async.commit_group;")

__device__ __forceinline__ uint32_t pack2h(float v0, float v1) {
    __half2 h(__float2half_rn(v0), __float2half_rn(v1));
    return *(uint32_t*)&h;
}

// ---------------------------------------------------------------------------
// Prep kernels
// ---------------------------------------------------------------------------
__global__ __launch_bounds__(256) void prep_x_kernel(const float* __restrict__ x) {
    int i = (blockIdx.x * 256 + threadIdx.x) * 4;
    float4 v = *(const float4*)&x[i];
    *(uint32_t*)&g_x[i]     = pack2h(v.x, v.y);
    *(uint32_t*)&g_x[i + 2] = pack2h(v.z, v.w);
}

// Transpose W [K, N] -> Wt [N, K] fp16 single
__global__ __launch_bounds__(256) void prep_w_kernel(
    const float* __restrict__ W, __half* __restrict__ Wt, int K, int N) {
    __shared__ float tile[32][33];
    int n0 = blockIdx.x * 32, k0 = blockIdx.y * 32;
    int tx = threadIdx.x & 31, ty = threadIdx.x >> 5;   // 32 x 8
    #pragma unroll
    for (int r = 0; r < 32; r += 8)
        tile[ty + r][tx] = W[(size_t)(k0 + ty + r) * N + n0 + tx];
    __syncthreads();
    #pragma unroll
    for (int r = 0; r < 32; r += 8) {
        float v = tile[tx][ty + r];
        Wt[(size_t)(n0 + ty + r) * K + k0 + tx] = __float2half_rn(v);
    }
}

// ---------------------------------------------------------------------------
// mma.sync fp16 GEMM: D = A * B^T + bias.
// 3-stage cp.async, BK=32; all issue-address math hoisted out of the loop.
// ---------------------------------------------------------------------------
#define GARR8  8192
#define GSTG   (2 * GARR8)          // 16384 per stage (A, B)
#define GSMEM  (3 * GSTG)           // 49152
#define QSCALE 0.1803368801111204f  // 0.125 * log2(e)

__device__ __forceinline__ uint32_t pk_off(int m, int c) {
    return (uint32_t)((m >> 1) * 128 + (m & 1) * 64 + ((c ^ ((m >> 1) & 3)) << 4));
}

__global__ __launch_bounds__(256, 2)
void gemm_f16_kernel(const __half* __restrict__ A,
                     const __half* __restrict__ Bw,
                     const float* __restrict__ bias,
                     float* __restrict__ out, int mode) {
    extern __shared__ __align__(16) char dynsm[];

    const int tid  = threadIdx.x;
    const int lane = tid & 31;
    const int wid  = tid >> 5;
    const int wm   = wid & 3;
    const int wn   = wid >> 2;
    const int n0 = blockIdx.x * 128;
    const int m0 = blockIdx.y * 128;

    const uint32_t uS = smem_u32(dynsm);

    float acc[2][8][4] = {};

    // ---- hoisted cp.async addressing (2 transfers per array per thread) ----
    const int m_0 = tid >> 2,          c_0 = tid & 3;
    const int m_1 = (tid + 256) >> 2,  c_1 = (tid + 256) & 3;
    const uint32_t so0 = pk_off(m_0, c_0);
    const uint32_t so1 = pk_off(m_1, c_1);
    const __half* pA0 = A  + (size_t)(m0 + m_0) * Cdim + c_0 * 8;
    const __half* pA1 = A  + (size_t)(m0 + m_1) * Cdim + c_1 * 8;
    const __half* pB0 = Bw + (size_t)(n0 + m_0) * Cdim + c_0 * 8;
    const __half* pB1 = Bw + (size_t)(n0 + m_1) * Cdim + c_1 * 8;

    auto issue = [&](int ch) {
        const uint32_t sb = uS + (uint32_t)(ch % 3) * GSTG;
        const int k0 = ch * 32;
        CP_ASYNC16(sb + so0,         pA0 + k0);
        CP_ASYNC16(sb + so1,         pA1 + k0);
        CP_ASYNC16(sb + GARR8 + so0, pB0 + k0);
        CP_ASYNC16(sb + GARR8 + so1, pB1 + k0);
        CP_COMMIT();
    };

    // per-lane ldmatrix address precomputes (row part + xor key)
    uint32_t arow[2], axor[2], brow[4], bxor[4];
    #pragma unroll
    for (int mt = 0; mt < 2; ++mt) {
        int m = wm * 32 + mt * 16 + (lane & 15);
        arow[mt] = (uint32_t)((m >> 1) * 128 + (m & 1) * 64);
        axor[mt] = (uint32_t)((m >> 1) & 3);
    }
    #pragma unroll
    for (int np = 0; np < 4; ++np) {
        int n = wn * 64 + np * 16 + (lane & 15);
        brow[np] = (uint32_t)((n >> 1) * 128 + (n & 1) * 64);
        bxor[np] = (uint32_t)((n >> 1) & 3);
    }
    const int chalf = lane >> 4;

    const int NCH = Cdim / 32;
    issue(0);
    issue(1);

    for (int ch = 0; ch < NCH; ++ch) {
        if (ch + 1 < NCH) { asm volatile("cp.async.wait_group 1;"); }
        else              { asm volatile("cp.async.wait_group 0;"); }
        __syncthreads();
        if (ch + 2 < NCH) issue(ch + 2);

        const uint32_t sb = uS + (uint32_t)(ch % 3) * GSTG;
        const uint32_t sA = sb, sB = sb + GARR8;

        #pragma unroll
        for (int kk = 0; kk < 2; ++kk) {
            const int cix = kk * 2 + chalf;
            uint32_t ah[8], bh[16];
            #pragma unroll
            for (int mt = 0; mt < 2; ++mt) {
                uint32_t ao = arow[mt] + (uint32_t)((cix ^ axor[mt]) << 4);
                LDSM4(ah + mt * 4, sA + ao);
            }
            #pragma unroll
            for (int np = 0; np < 4; ++np) {
                uint32_t bo = brow[np] + (uint32_t)((cix ^ bxor[np]) << 4);
                LDSM4(bh + np * 4, sB + bo);
            }
            #pragma unroll
            for (int np = 0; np < 4; ++np)
                #pragma unroll
                for (int mt = 0; mt < 2; ++mt)
                    #pragma unroll
                    for (int hf = 0; hf < 2; ++hf)
                        MMA_F16(acc[mt][np * 2 + hf], ah + mt * 4,
                                bh[np * 4 + hf], bh[np * 4 + 2 + hf]);
        }
    }

    if (mode == 0) {
        const int ncol0 = n0 + wn * 64;
        const int which = ncol0 >> 10;
        const int hh    = (ncol0 & 1023) >> 6;
        __half* dst = (which == 0) ? g_q : ((which == 1) ? g_k : g_v);
        const float qs = (which == 0) ? QSCALE : 1.0f;
        #pragma unroll
        for (int mt = 0; mt < 2; ++mt) {
            const int rg0 = m0 + wm * 32 + mt * 16 + (lane >> 2);
            const int bb  = rg0 >> 11;
            const int t0  = rg0 & 2047;
            const size_t rbase = (((size_t)bb * Hn + hh) * Tdim + t0) * HDd;
            #pragma unroll
            for (int nt = 0; nt < 8; ++nt) {
                const int d = nt * 8 + (lane & 3) * 2;
                const float2 bv = *(const float2*)&bias[ncol0 + d];
                *(uint32_t*)&dst[rbase + d] =
                    pack2h((acc[mt][nt][0] + bv.x) * qs, (acc[mt][nt][1] + bv.y) * qs);
                *(uint32_t*)&dst[rbase + 8 * HDd + d] =
                    pack2h((acc[mt][nt][2] + bv.x) * qs, (acc[mt][nt][3] + bv.y) * qs);
            }
        }
    } else {
        #pragma unroll
        for (int mt = 0; mt < 2; ++mt) {
            const int rg0 = m0 + wm * 32 + mt * 16 + (lane >> 2);
            #pragma unroll
            for (int nt = 0; nt < 8; ++nt) {
                const int ncol = n0 + wn * 64 + nt * 8 + (lane & 3) * 2;
                const float2 bv = *(const float2*)&bias[ncol];
                float2 v0, v1;
                v0.x = acc[mt][nt][0] + bv.x;
                v0.y = acc[mt][nt][1] + bv.y;
                v1.x = acc[mt][nt][2] + bv.x;
                v1.y = acc[mt][nt][3] + bv.y;
                size_t base = (size_t)rg0 * Cdim + ncol;
                *(float2*)&out[base]            = v0;
                *(float2*)&out[base + 8 * Cdim] = v1;
            }
        }
    }
}

// ---------------------------------------------------------------------------
// mma.sync causal flash attention: 4 warps x 32 q-rows, BQ=128, BKV=64.
// Q fragments cached in registers. 3-stage KV ring, ONE barrier per iter.
// Scores in log2 domain, exp2f softmax.
// ---------------------------------------------------------------------------
#define ARS 144                      // row stride bytes
#define AQ  0
#define AKV0 18432
#define KVSTG 18432                  // per-stage (K 9216 + V 9216)
#define ASMEM (AKV0 + 3 * KVSTG)     // 73728

__global__ __launch_bounds__(128, 2) void attn_mma_kernel() {
    extern __shared__ __align__(16) char asmem[];
    const int tid = threadIdx.x;
    const int lane = tid & 31;
    const int w = tid >> 5;                       // 0..3, owns 32 q rows
    const int qt = gridDim.x - 1 - blockIdx.x;    // heavy tiles first
    const int bh = blockIdx.y;

    const uint32_t uS = smem_u32(asmem);
    const size_t hbase = (size_t)bh * Tdim * HDd;
    const __half* qq = g_q + hbase;

    // ---- hoisted KV issue addressing (4 transfers per array per thread) ----
    const int kv_row = tid >> 3;          // base row (0..15), +16 per it
    const int kv_c   = tid & 7;
    const uint32_t kv_dst0 = (uint32_t)(kv_row * ARS + kv_c * 16);
    const __half* pK0 = g_k + hbase + (size_t)kv_row * HDd + kv_c * 8;
    const __half* pV0 = g_v + hbase + (size_t)kv_row * HDd + kv_c * 8;

    auto issue_kv = [&](int kt) {
        const uint32_t sb = uS + AKV0 + (uint32_t)(kt % 3) * KVSTG;
        const size_t koff = (size_t)kt * 64 * HDd;
        #pragma unroll
        for (int it = 0; it < 4; ++it) {
            const uint32_t dst = kv_dst0 + (uint32_t)(it * 16 * ARS);
            const size_t src = koff + (size_t)(it * 16) * HDd;
            CP_ASYNC16(sb + dst,        pK0 + src);
            CP_ASYNC16(sb + 9216 + dst, pV0 + src);
        }
        CP_COMMIT();
    };

    // Q tile load (committed together with KV stage 0)
    #pragma unroll
    for (int it = 0; it < 8; ++it) {
        int idx = tid + it * 128;
        int row = idx >> 3, c = idx & 7;
        uint32_t dst = row * ARS + c * 16;
        size_t src = (size_t)(qt * 128 + row) * HDd + c * 8;
        CP_ASYNC16(uS + AQ + dst, qq + src);
    }
    issue_kv(0);

    const int r4 = lane >> 2;
    const int c2 = (lane & 3) * 2;
    float m[4], l[4];
    #pragma unroll
    for (int i = 0; i < 4; ++i) { m[i] = -1e30f; l[i] = 0.f; }
    float O[2][8][4] = {};
    uint32_t aq[2][4][4];          // Q fragments cached: [mt][k16][4]

    const int nkt = 2 * qt + 2;
    for (int kt = 0; kt < nkt; ++kt) {
        const bool more = (kt + 1 < nkt);
        if (more) issue_kv(kt + 1);
        if (more) { asm volatile("cp.async.wait_group 1;"); }
        else      { asm volatile("cp.async.wait_group 0;"); }
        __syncthreads();   // single barrier per iteration (3-stage ring safe)

        if (kt == 0) {
            #pragma unroll
            for (int mt = 0; mt < 2; ++mt)
                #pragma unroll
                for (int k16 = 0; k16 < 4; ++k16) {
                    uint32_t qoff = (uint32_t)((w * 32 + mt * 16 + (lane & 15)) * ARS
                                               + (lane >> 4) * 16 + k16 * 32);
                    LDSM4(aq[mt][k16], uS + AQ + qoff);
                }
        }

        const uint32_t kvb = uS + AKV0 + (uint32_t)(kt % 3) * KVSTG;
        const uint32_t uK = kvb, uV = kvb + 9216;

        // ---- S = Q K^T (single fp16, Q from registers) ----
        float S[2][8][4] = {};
        #pragma unroll
        for (int k16 = 0; k16 < 4; ++k16) {
            const uint32_t kfrag =
                (uint32_t)((lane & 15) * ARS + (lane >> 4) * 16 + k16 * 32);
            uint32_t bk[16];
            #pragma unroll
            for (int kp = 0; kp < 4; ++kp)
                LDSM4(bk + kp * 4, uK + kfrag + (uint32_t)(kp * 16) * ARS);
            #pragma unroll
            for (int kp = 0; kp < 4; ++kp)
                #pragma unroll
                for (int mt = 0; mt < 2; ++mt)
                    #pragma unroll
                    for (int hf = 0; hf < 2; ++hf)
                        MMA_F16(S[mt][kp * 2 + hf], aq[mt][k16],
                                bk[kp * 4 + hf], bk[kp * 4 + 2 + hf]);
        }

        // ---- causal mask ----
        if (kt * 64 + 63 > qt * 128 + w * 32) {
            #pragma unroll
            for (int mt = 0; mt < 2; ++mt) {
                const int row0 = qt * 128 + w * 32 + mt * 16 + r4;
                #pragma unroll
                for (int j = 0; j < 8; ++j) {
                    const int cb = kt * 64 + j * 8 + c2;
                    if (cb     > row0)     S[mt][j][0] = -1e30f;
                    if (cb + 1 > row0)     S[mt][j][1] = -1e30f;
                    if (cb     > row0 + 8) S[mt][j][2] = -1e30f;
                    if (cb + 1 > row0 + 8) S[mt][j][3] = -1e30f;
                }
            }
        }

        // ---- online softmax (log2 domain, exp2f) ----
        #pragma unroll
        for (int mt = 0; mt < 2; ++mt) {
            float mt0 = -1e30f, mt1 = -1e30f;
            #pragma unroll
            for (int j = 0; j < 8; ++j) {
                mt0 = fmaxf(mt0, fmaxf(S[mt][j][0], S[mt][j][1]));
                mt1 = fmaxf(mt1, fmaxf(S[mt][j][2], S[mt][j][3]));
            }
            mt0 = fmaxf(mt0, __shfl_xor_sync(0xffffffffu, mt0, 1));
            mt0 = fmaxf(mt0, __shfl_xor_sync(0xffffffffu, mt0, 2));
            mt1 = fmaxf(mt1, __shfl_xor_sync(0xffffffffu, mt1, 1));
            mt1 = fmaxf(mt1, __shfl_xor_sync(0xffffffffu, mt1, 2));
            const float mn0 = fmaxf(m[mt * 2],     mt0);
            const float mn1 = fmaxf(m[mt * 2 + 1], mt1);
            const float sf0 = exp2f(m[mt * 2]     - mn0);
            const float sf1 = exp2f(m[mt * 2 + 1] - mn1);
            m[mt * 2] = mn0; m[mt * 2 + 1] = mn1;

            float rs0 = 0.f, rs1 = 0.f;
            #pragma unroll
            for (int j = 0; j < 8; ++j) {
                S[mt][j][0] = exp2f(S[mt][j][0] - mn0);
                S[mt][j][1] = exp2f(S[mt][j][1] - mn0);
                S[mt][j][2] = exp2f(S[mt][j][2] - mn1);
                S[mt][j][3] = exp2f(S[mt][j][3] - mn1);
                rs0 += S[mt][j][0] + S[mt][j][1];
                rs1 += S[mt][j][2] + S[mt][j][3];
            }
            rs0 += __shfl_xor_sync(0xffffffffu, rs0, 1);
            rs0 += __shfl_xor_sync(0xffffffffu, rs0, 2);
            rs1 += __shfl_xor_sync(0xffffffffu, rs1, 1);
            rs1 += __shfl_xor_sync(0xffffffffu, rs1, 2);
            l[mt * 2]     = l[mt * 2]     * sf0 + rs0;
            l[mt * 2 + 1] = l[mt * 2 + 1] * sf1 + rs1;
            #pragma unroll
            for (int j = 0; j < 8; ++j) {
                O[mt][j][0] *= sf0; O[mt][j][1] *= sf0;
                O[mt][j][2] *= sf1; O[mt][j][3] *= sf1;
            }
        }

        // ---- O += P V (single fp16) ----
        #pragma unroll
        for (int s = 0; s < 4; ++s) {
            const uint32_t vrow =
                (uint32_t)((s * 16 + (lane & 7) + ((lane >> 3) & 1) * 8) * ARS
                           + (lane >> 4) * 16);
            uint32_t bv[16];
            #pragma unroll
            for (int np = 0; np < 4; ++np)
                LDSM4T(bv + np * 4, uV + vrow + np * 32);
            #pragma unroll
            for (int mt = 0; mt < 2; ++mt) {
                uint32_t ph[4];
                ph[0] = pack2h(S[mt][2 * s][0],     S[mt][2 * s][1]);
                ph[1] = pack2h(S[mt][2 * s][2],     S[mt][2 * s][3]);
                ph[2] = pack2h(S[mt][2 * s + 1][0], S[mt][2 * s + 1][1]);
                ph[3] = pack2h(S[mt][2 * s + 1][2], S[mt][2 * s + 1][3]);
                #pragma unroll
                for (int np = 0; np < 4; ++np) {
                    MMA_F16(O[mt][np * 2],     ph, bv[np * 4],     bv[np * 4 + 1]);
                    MMA_F16(O[mt][np * 2 + 1], ph, bv[np * 4 + 2], bv[np * 4 + 3]);
                }
            }
        }
    }

    // ---- normalize + write y (fp16 single for proj) ----
    const int b = bh >> 4, h = bh & 15;
    #pragma unroll
    for (int mt = 0; mt < 2; ++mt) {
        const float inv0 = 1.f / l[mt * 2];
        const float inv1 = 1.f / l[mt * 2 + 1];
        const int rg0 = b * Tdim + qt * 128 + w * 32 + mt * 16 + r4;
        const size_t base0 = (size_t)rg0 * Cdim + h * HDd;
        #pragma unroll
        for (int j = 0; j < 8; ++j) {
            const int d = j * 8 + c2;
            *(uint32_t*)&g_y[base0 + d] =
                pack2h(O[mt][j][0] * inv0, O[mt][j][1] * inv0);
            *(uint32_t*)&g_y[base0 + 8 * Cdim + d] =
                pack2h(O[mt][j][2] * inv1, O[mt][j][3] * inv1);
        }
    }
}

// ---------------------------------------------------------------------------
extern "C" void kernel_launch(void* const* d_in, const int* in_sizes, int n_in,
                              void* d_out, int out_size) {
    const float* x      = (const float*)d_in[0];
    const float* w_attn = (const float*)d_in[1];
    const float* b_attn = (const float*)d_in[2];
    const float* w_proj = (const float*)d_in[3];
    const float* b_proj = (const float*)d_in[4];
    float* out = (float*)d_out;

    static bool attr_set = false;
    if (!attr_set) {
        cudaFuncSetAttribute(gemm_f16_kernel,
                             cudaFuncAttributeMaxDynamicSharedMemorySize, GSMEM);
        cudaFuncSetAttribute(attn_mma_kernel,
                             cudaFuncAttributeMaxDynamicSharedMemorySize, ASMEM);
        attr_set = true;
    }

    __half *xp, *wa, *wp, *yp;
    cudaGetSymbolAddress((void**)&xp, g_x);
    cudaGetSymbolAddress((void**)&wa, g_wa);
    cudaGetSymbolAddress((void**)&wp, g_wp);
    cudaGetSymbolAddress((void**)&yp, g_y);

    // Prep: convert x to fp16, transpose weights to fp16 [N][K]
    prep_x_kernel<<<Mrows * Cdim / (256 * 4), 256>>>(x);
    {
        dim3 ga(N3 / 32, Cdim / 32);
        prep_w_kernel<<<ga, 256>>>(w_attn, wa, Cdim, N3);
        dim3 gp(Cdim / 32, Cdim / 32);
        prep_w_kernel<<<gp, 256>>>(w_proj, wp, Cdim, Cdim);
    }

    // QKV GEMM -> q (x0.125*log2e) / k / v fp16 head-major
    dim3 g1(N3 / 128, Mrows / 128);     // 24 x 32
    gemm_f16_kernel<<<g1, 256, GSMEM>>>(xp, wa, b_attn, nullptr, 0);

    // Attention (tensor-core, 4-warp CTAs, 3-stage KV, single barrier/iter)
    dim3 g2(Tdim / 128, Bdim * Hn);     // 16 x 32, 128-thread CTAs
    attn_mma_kernel<<<g2, 128, ASMEM>>>();

    // Proj GEMM
    dim3 g3(Cdim / 128, Mrows / 128);   // 8 x 32
    gemm_f16_kernel<<<g3, 256, GSMEM>>>(yp, wp, b_proj, out, 1);
}